// round 3
// baseline (speedup 1.0000x reference)
#include <cuda_runtime.h>

#define B_ 32
#define L_ 128
#define D_ 48
#define R_ 64
#define OUTSZ (B_*R_*D_)   // 98304

// 8 partial slices (one per L-split) of (B,R,D), plus last-block counters
__device__ float g_scratch[8 * OUTSZ];
__device__ int   g_cnt[32];

#define EX2(d, a) asm("ex2.approx.ftz.f32 %0, %1;" : "=f"(d) : "f"(a))

__global__ __launch_bounds__(192, 2) void alnn_fused(
    const float* __restrict__ X, const float* __restrict__ T,
    const float* __restrict__ M, const float* __restrict__ DT,
    const float* __restrict__ P, const float* __restrict__ alpha,
    const float* __restrict__ w_t, const float* __restrict__ b_t,
    const float* __restrict__ w_v, const float* __restrict__ b_v,
    float* __restrict__ out)
{
    // Grid: 256 = 4 bg x 8 rg x 8 ls. Block: 192 = 4 lgroups x 48 d.
    const int c  = blockIdx.x;
    const int ls = c & 7;
    const int rg = (c >> 3) & 7;
    const int bg = c >> 6;

    const int tid = threadIdx.x;
    const int d = tid % D_;
    const int g = tid / D_;          // 0..3
    const int b0 = bg * 8;
    const int r0 = rg * 8;
    const int l0 = ls * 16 + g * 4;  // 4 l's per thread

    // -relu(alpha[r])*log2(e), warp-uniform loads
    float naa[8];
#pragma unroll
    for (int ri = 0; ri < 8; ri++)
        naa[ri] = -fmaxf(alpha[r0 + ri], 0.0f) * 1.4426950408889634f;

    float acc[8][8];                 // [b][ri]
#pragma unroll
    for (int b = 0; b < 8; b++)
#pragma unroll
        for (int ri = 0; ri < 8; ri++) acc[b][ri] = 0.0f;

#pragma unroll 1
    for (int j = 0; j < 4; j++) {
        const int l = l0 + j;

        // Load 8 batches' inputs at (l,d): 40 independent LDGs up front
        float xv[8], xr[8], tv[8], mv[8], dtv[8], pv[8];
#pragma unroll
        for (int b = 0; b < 8; b++) {
            const int idx = ((b0 + b) * L_ + l) * D_ + d;
            xv[b]  = X[idx];
            tv[b]  = T[idx];
            mv[b]  = M[idx];
            dtv[b] = DT[idx];
            pv[b]  = P[idx];
            xr[b]  = fmaxf(xv[b], 0.0f);
        }

        const int wbase = (r0 * L_ + l) * D_ + d;

        // Prefetch weights for ri=0
        float cw[7];
        {
            const float* wt = w_t + (size_t)wbase * 5;
            cw[0] = wt[0]; cw[1] = wt[1]; cw[2] = wt[2]; cw[3] = wt[3]; cw[4] = wt[4];
            cw[5] = b_t[wbase];
            cw[6] = w_v[wbase];
        }

#pragma unroll
        for (int ri = 0; ri < 8; ri++) {
            // Prefetch ri+1's weights while computing ri
            float nw[7];
            if (ri < 7) {
                const int wi = wbase + (ri + 1) * (L_ * D_);
                const float* wt = w_t + (size_t)wi * 5;
                nw[0] = wt[0]; nw[1] = wt[1]; nw[2] = wt[2]; nw[3] = wt[3]; nw[4] = wt[4];
                nw[5] = b_t[wi];
                nw[6] = w_v[wi];
            }

            const float w0 = cw[0], w1 = cw[1], w2 = cw[2], w3 = cw[3], w4 = cw[4];
            const float bt5 = 5.0f * cw[5];
            const float wv  = cw[6];
            const float rr  = (float)(r0 + ri) * (48.0f / 63.0f);
            const float na  = naa[ri];

#pragma unroll
            for (int b = 0; b < 8; b++) {
                const float dd  = tv[b] - rr;
                const float arg = na * fabsf(dd);      // FMUL with |src| modifier
                float k;
                EX2(k, arg);
                const float inten = xr[b] * k;         // relu(x)*k == relu(x*k)
                float s = fmaf(w0, xv[b], bt5);
                s = fmaf(w1, inten,  s);
                s = fmaf(w2, mv[b],  s);
                s = fmaf(w3, dtv[b], s);
                s = fmaf(w4, pv[b],  s);
                s = fmaxf(s, 0.0f);
                acc[b][ri] = fmaf(wv, s, acc[b][ri]);
            }

#pragma unroll
            for (int q = 0; q < 7; q++) cw[q] = nw[q];
        }
    }

    // Intra-CTA reduction over the 4 l-groups, in 2 halves of 4 batches
    __shared__ float sm[4 * 4 * 8 * D_];   // [g][bl][ri][d] = 24KB
    __shared__ int s_last;

#pragma unroll 1
    for (int h = 0; h < 2; h++) {
#pragma unroll
        for (int bl = 0; bl < 4; bl++)
#pragma unroll
            for (int ri = 0; ri < 8; ri++)
                sm[((g * 4 + bl) * 8 + ri) * D_ + d] = acc[h * 4 + bl][ri];
        __syncthreads();
#pragma unroll
        for (int k = 0; k < 8; k++) {
            const int idx = k * 192 + tid;             // 0..1535
            const float s = sm[idx] + sm[1536 + idx] + sm[2*1536 + idx] + sm[3*1536 + idx];
            const int dd = idx % D_;
            const int ri = (idx / D_) & 7;
            const int bl = idx / (8 * D_);
            const int b = b0 + h * 4 + bl;
            const int r = r0 + ri;
            g_scratch[ls * OUTSZ + (b * R_ + r) * D_ + dd] = s;
        }
        __syncthreads();
    }

    // Last CTA of this (bg,rg) group reduces the 8 L-slices and writes out
    if (tid == 0) {
        __threadfence();
        const int v = atomicAdd(&g_cnt[bg * 8 + rg], 1);
        s_last = (v == 7);
    }
    __syncthreads();
    if (!s_last) return;

    if (tid == 0) g_cnt[bg * 8 + rg] = 0;   // reset for next graph replay
    __threadfence();                         // acquire: see other CTAs' scratch

#pragma unroll 2
    for (int k = 0; k < 16; k++) {
        const int idx = k * 192 + tid;       // 0..3071 within the (bg,rg) tile
        const int dd = idx % D_;
        const int ri = (idx / D_) & 7;
        const int bl = idx / (8 * D_);
        const int o = ((b0 + bl) * R_ + (r0 + ri)) * D_ + dd;
        float s = 128.0f * b_v[(r0 + ri) * D_ + dd];   // b_v broadcast over L -> x128
#pragma unroll
        for (int sl = 0; sl < 8; sl++)
            s += g_scratch[sl * OUTSZ + o];
        out[o] = fmaxf(s, 0.0f);
    }
}

extern "C" void kernel_launch(void* const* d_in, const int* in_sizes, int n_in,
                              void* d_out, int out_size)
{
    const float* X     = (const float*)d_in[0];
    const float* T     = (const float*)d_in[1];
    const float* M     = (const float*)d_in[2];
    const float* DT    = (const float*)d_in[3];
    const float* P     = (const float*)d_in[4];
    const float* alpha = (const float*)d_in[5];
    const float* w_t   = (const float*)d_in[6];
    const float* b_t   = (const float*)d_in[7];
    const float* w_v   = (const float*)d_in[8];
    const float* b_v   = (const float*)d_in[9];
    float* out = (float*)d_out;

    alnn_fused<<<256, 192>>>(X, T, M, DT, P, alpha, w_t, b_t, w_v, b_v, out);
}